// round 5
// baseline (speedup 1.0000x reference)
#include <cuda_runtime.h>
#include <cuda_bf16.h>
#include <cstdint>

// ============================================================================
// ContrastiveLoss via warp-level mma.sync bf16 m16n8k16 + ldmatrix.
// Round 5: split prefetch (A then B) to keep live regs <= 128 -> no spills,
// 2 CTAs/SM. Mainloop otherwise identical to the passing round-4 kernel.
// scores[b,c] = sum_r max_{w<cl[c]} <A[b,r,:], S[c,w,:]> / (obj[b]+1e-6)
// ============================================================================

namespace {
constexpr int D = 1024;
constexpr int BM = 128;
constexpr int BK = 32;                  // k elems per smem chunk (2 x k16 steps)
constexpr int NCHUNK = D / BK;          // 32
constexpr int SROW = 40;                // bf16 elems per smem row (80 B)
constexpr int STAGE_BYTES = BM * SROW * 2;   // 10240
}

__device__ float g_scores[128 * 128];
__device__ float g_loss;

__global__ void zero_kernel(int n) {
    int i = blockIdx.x * blockDim.x + threadIdx.x;
    if (i < n) g_scores[i] = 0.0f;
    if (i == 0) g_loss = 0.0f;
}

__device__ __forceinline__ uint32_t smem_u32(const void* p) {
    uint32_t a;
    asm("{ .reg .u64 t; cvta.to.shared.u64 t, %1; cvt.u32.u64 %0, t; }" : "=r"(a) : "l"(p));
    return a;
}
__device__ __forceinline__ uint32_t pack_bf16(float lo, float hi) {
    __nv_bfloat162 h = __floats2bfloat162_rn(lo, hi);
    return *reinterpret_cast<uint32_t*>(&h);
}
__device__ __forceinline__ void ldsm_x4(uint32_t addr, uint32_t* r) {
    asm volatile("ldmatrix.sync.aligned.m8n8.x4.shared.b16 {%0,%1,%2,%3}, [%4];"
                 : "=r"(r[0]), "=r"(r[1]), "=r"(r[2]), "=r"(r[3]) : "r"(addr));
}
__device__ __forceinline__ void mma_bf16(float* c, const uint32_t* a, const uint32_t* b) {
    asm volatile(
        "mma.sync.aligned.m16n8k16.row.col.f32.bf16.bf16.f32 "
        "{%0,%1,%2,%3}, {%4,%5,%6,%7}, {%8,%9}, {%0,%1,%2,%3};"
        : "+f"(c[0]), "+f"(c[1]), "+f"(c[2]), "+f"(c[3])
        : "r"(a[0]), "r"(a[1]), "r"(a[2]), "r"(a[3]), "r"(b[0]), "r"(b[1]));
}

// A: [Bsz, R, D] -> M = Bsz*R rows (multiple of 128). Bm: [Bsz, W, D].
// CTA tile: 128 rows x 128 cols; cols = (128/WPAD) captions padded to WPAD words.
template <int WPAD>
__global__ void __launch_bounds__(256, 2)
xattn_bf16_kernel(const float* __restrict__ A, const float* __restrict__ Bm,
                  const int* __restrict__ cap_lens, const int* __restrict__ obj_nums,
                  int R, int W, int Bsz)
{
    constexpr int LOGW = (WPAD == 64) ? 6 : 5;
    constexpr int CAPS_PER_TILE = 128 / WPAD;
    constexpr int CAPS_PER_WARP = 64 / WPAD;     // 1 or 2

    // stages: [0]=A0 [1]=A1 [2]=B0 [3]=B1
    __shared__ __align__(16) unsigned char smraw[4][STAGE_BYTES];
    const uint32_t sbase = smem_u32(smraw);

    const int tid  = threadIdx.x;
    const int wid  = tid >> 5;
    const int lane = tid & 31;
    const int g = lane >> 2;
    const int t = lane & 3;
    const int wm = wid & 3;           // warp rows wm*32..
    const int wn = wid >> 2;          // warp cols wn*64..
    const int m0 = blockIdx.x * BM;
    const int cbase = blockIdx.y * CAPS_PER_TILE;

    // ---- loader mapping: 2 threads per row, 16 k-floats each
    const int lr = tid >> 1;                  // 0..127
    const int lk = (tid & 1) << 4;            // 0 or 16
    const float* ga = A + (size_t)(m0 + lr) * D + lk;
    const int bc = cbase + (lr >> LOGW);
    const int bw = lr & (WPAD - 1);
    const bool bvalid = bw < W;
    const float* gb = Bm + ((size_t)bc * W + bw) * D + lk;
    const int soff = lr * (SROW * 2) + lk * 2;   // byte offset within stage

    float acc[2][8][4];
#pragma unroll
    for (int mt = 0; mt < 2; mt++)
#pragma unroll
        for (int nt = 0; nt < 8; nt++)
#pragma unroll
            for (int e = 0; e < 4; e++) acc[mt][nt][e] = 0.0f;

    // ---- ldmatrix per-lane base byte offsets (within a stage)
    uint32_t aoff[2];
#pragma unroll
    for (int mt = 0; mt < 2; mt++)
        aoff[mt] = (uint32_t)((wm * 32 + mt * 16 + (lane & 15)) * (SROW * 2) + ((lane >> 4) << 4));
    uint32_t boff[4];
#pragma unroll
    for (int nb = 0; nb < 4; nb++) {
        const int n_local = (lane & 7) + ((lane & 16) ? 8 : 0);
        const int kb = (lane & 8) ? 16 : 0;
        boff[nb] = (uint32_t)((wn * 64 + nb * 16 + n_local) * (SROW * 2) + kb);
    }

    const float4 fz = make_float4(0.f, 0.f, 0.f, 0.f);

    // 16-float prefetch buffer (shared between A-phase and B-phase; each dies
    // before the other is born, so the compiler can overlay them)
    float4 fr[4];

    auto loadA = [&](int k0) {
#pragma unroll
        for (int i = 0; i < 4; i++) fr[i] = *(const float4*)(ga + k0 + i * 4);
    };
    auto loadB = [&](int k0) {
#pragma unroll
        for (int i = 0; i < 4; i++) fr[i] = bvalid ? *(const float4*)(gb + k0 + i * 4) : fz;
    };
    auto storeStage = [&](int stage) {   // cvt fr -> bf16, 2x STS.128
        uint32_t p[8];
#pragma unroll
        for (int i = 0; i < 4; i++) {
            p[2 * i]     = pack_bf16(fr[i].x, fr[i].y);
            p[2 * i + 1] = pack_bf16(fr[i].z, fr[i].w);
        }
        *(uint4*)(&smraw[stage][soff])      = make_uint4(p[0], p[1], p[2], p[3]);
        *(uint4*)(&smraw[stage][soff + 16]) = make_uint4(p[4], p[5], p[6], p[7]);
    };

    auto do_ks = [&](int buf, int ks) {
        const uint32_t ko = (uint32_t)(ks * 32);      // 16 bf16 = 32 bytes
        const uint32_t abase = sbase + buf * STAGE_BYTES;
        const uint32_t bbase = sbase + (2 + buf) * STAGE_BYTES;
        uint32_t afr[2][4];
#pragma unroll
        for (int mt = 0; mt < 2; mt++) ldsm_x4(abase + aoff[mt] + ko, afr[mt]);
        uint32_t bfr[4][4];
#pragma unroll
        for (int nb = 0; nb < 4; nb++) ldsm_x4(bbase + boff[nb] + ko, bfr[nb]);
#pragma unroll
        for (int mt = 0; mt < 2; mt++)
#pragma unroll
            for (int nt = 0; nt < 8; nt++)
                mma_bf16(acc[mt][nt], afr[mt], &bfr[nt >> 1][(nt & 1) * 2]);
    };

    // prologue: fill buffer 0
    loadA(0); storeStage(0);
    loadB(0); storeStage(2);
    __syncthreads();

    for (int ch = 0; ch < NCHUNK; ch++) {
        const int buf = ch & 1;
        const int nxt = buf ^ 1;
        const bool more = (ch + 1 < NCHUNK);
        const int k1 = (ch + 1) * BK;

        if (more) loadA(k1);           // 4 LDG.128 (A next)
        do_ks(buf, 0);                 // hides A latency
        if (more) { storeStage(nxt); loadB(k1); }   // store A-next, issue B-next
        do_ks(buf, 1);                 // hides B latency
        if (more) storeStage(2 + nxt); // store B-next
        __syncthreads();
    }

    // ---- epilogue: masked max over caption words, reduce over t-lanes, atomics
    int clv[2];
#pragma unroll
    for (int cap = 0; cap < CAPS_PER_WARP; cap++)
        clv[cap] = cap_lens[cbase + wn * CAPS_PER_WARP + cap];

    float mx[2][2][CAPS_PER_WARP];
#pragma unroll
    for (int mt = 0; mt < 2; mt++)
#pragma unroll
        for (int h = 0; h < 2; h++)
#pragma unroll
            for (int cap = 0; cap < CAPS_PER_WARP; cap++)
                mx[mt][h][cap] = -1e30f;

#pragma unroll
    for (int mt = 0; mt < 2; mt++)
#pragma unroll
        for (int nt = 0; nt < 8; nt++)
#pragma unroll
            for (int e = 0; e < 2; e++) {
                const int wc = nt * 8 + 2 * t + e;            // 0..63 within warp cols
                const int cap = wc >> LOGW;
                const int wpos = wc & (WPAD - 1);
                if (wpos < clv[cap]) {
                    mx[mt][0][cap] = fmaxf(mx[mt][0][cap], acc[mt][nt][e]);
                    mx[mt][1][cap] = fmaxf(mx[mt][1][cap], acc[mt][nt][2 + e]);
                }
            }

#pragma unroll
    for (int mt = 0; mt < 2; mt++)
#pragma unroll
        for (int h = 0; h < 2; h++)
#pragma unroll
            for (int cap = 0; cap < CAPS_PER_WARP; cap++) {
                float v = mx[mt][h][cap];
                v = fmaxf(v, __shfl_xor_sync(0xffffffffu, v, 1));
                v = fmaxf(v, __shfl_xor_sync(0xffffffffu, v, 2));
                if (t == 0) {
                    const int row = m0 + wm * 32 + mt * 16 + h * 8 + g;
                    const int b = row / R;
                    const float denom = (float)obj_nums[b] + 1e-6f;
                    const int c = cbase + wn * CAPS_PER_WARP + cap;
                    atomicAdd(&g_scores[b * Bsz + c], __fdividef(v, denom));
                }
            }
}

__global__ void loss_kernel(int Bsz) {
    __shared__ float red[256];
    const int tid = threadIdx.x;
    const int n = Bsz * Bsz;
    float sum = 0.0f;
    for (int idx = blockIdx.x * blockDim.x + tid; idx < n; idx += gridDim.x * blockDim.x) {
        const int i = idx / Bsz;
        const int j = idx - i * Bsz;
        if (i != j) {
            const float sc = g_scores[idx];
            const float di = g_scores[i * Bsz + i];
            const float dj = g_scores[j * Bsz + j];
            sum += fmaxf(0.0f, 0.2f + sc - di);
            sum += fmaxf(0.0f, 0.2f + sc - dj);
        }
    }
    red[tid] = sum;
    __syncthreads();
    for (int s = 128; s > 0; s >>= 1) {
        if (tid < s) red[tid] += red[tid + s];
        __syncthreads();
    }
    if (tid == 0) atomicAdd(&g_loss, red[0]);
}

__global__ void write_out_kernel(float* out, int out_size, int n) {
    const int i = blockIdx.x * blockDim.x + threadIdx.x;
    if (i >= out_size) return;
    if (out_size == n) { out[i] = g_scores[i]; return; }
    if (out_size == 1) { out[0] = g_loss; return; }
    if (i == 0) { out[0] = g_loss; return; }
    const int j = i - 1;
    out[i] = (j < n) ? g_scores[j] : 0.0f;
}

extern "C" void kernel_launch(void* const* d_in, const int* in_sizes, int n_in,
                              void* d_out, int out_size) {
    const float* im   = (const float*)d_in[0];
    const int*   im_l = (const int*)  d_in[1];
    const float* s    = (const float*)d_in[2];
    const int*   s_l  = (const int*)  d_in[3];
    const float* pred = (const float*)d_in[4];
    const int*   pr_l = (const int*)  d_in[5];
    const float* sp   = (const float*)d_in[6];
    const int*   sp_l = (const int*)  d_in[7];

    const int Bsz = in_sizes[1];                 // 128
    const int R   = in_sizes[0] / (Bsz * D);     // 36
    const int W   = in_sizes[2] / (Bsz * D);     // 50
    const int Rp  = in_sizes[4] / (Bsz * D);     // 25
    const int Wp  = in_sizes[6] / (Bsz * D);     // 30

    zero_kernel<<<(Bsz * Bsz + 255) / 256, 256>>>(Bsz * Bsz);

    const int M1 = Bsz * R;    // 4608
    const int M2 = Bsz * Rp;   // 3200
    // part 1: W=50 -> pad 64, 2 captions per 128-col tile
    dim3 g1(M1 / BM, (Bsz * 64) / 128);
    xattn_bf16_kernel<64><<<g1, 256>>>(im, s, s_l, im_l, R, W, Bsz);
    // part 2: W=30 -> pad 32, 4 captions per tile
    dim3 g2(M2 / BM, (Bsz * 32) / 128);
    xattn_bf16_kernel<32><<<g2, 256>>>(pred, sp, sp_l, pr_l, Rp, Wp, Bsz);

    loss_kernel<<<32, 256>>>(Bsz);
    write_out_kernel<<<(out_size + 255) / 256, 256>>>((float*)d_out, out_size, Bsz * Bsz);
}